// round 3
// baseline (speedup 1.0000x reference)
#include <cuda_runtime.h>
#include <cstdint>

#define N_NODES 100000
#define D_DIM 16
#define F_FILT 8
#define NNZ_E 1600000
#define CAP 96        // Poisson(16) over 100k rows: P(count >= 96) ~ e^-92, effectively zero
#define CW_STRIDE 32  // combined record: [0..15]=LTx row, [16..23]=wav, pad to 128B

// Static device scratch (no allocation allowed in kernel_launch)
__device__ float g_cw[(size_t)N_NODES * CW_STRIDE];   // combined {LTx | wav} per node
__device__ int   g_rcnt[N_NODES];                     // edges per output row
__device__ int   g_ccnt[N_NODES];                     // edges per column
__device__ uint2 g_rbuf[(size_t)N_NODES * CAP];       // per-row packed (col, val)
__device__ uint2 g_cbuf[(size_t)N_NODES * CAP];       // per-col packed (row, val)

// Kernel 1: per node — wavelet bank via successive squaring; zero both counters.
__global__ void prep_kernel(const float* __restrict__ eig) {
    int i = blockIdx.x * blockDim.x + threadIdx.x;
    if (i >= N_NODES) return;

    float p = expf(-eig[i]);   // exp(-eig)^(2^0)
    float wav[F_FILT];
#pragma unroll
    for (int f = 0; f < F_FILT; f++) {
        float nx = p * p;      // successive squaring -> powers 2^f
        wav[f] = p - nx;
        p = nx;
    }
    float4* wv = reinterpret_cast<float4*>(g_cw + (size_t)i * CW_STRIDE + D_DIM);
    wv[0] = make_float4(wav[0], wav[1], wav[2], wav[3]);
    wv[1] = make_float4(wav[4], wav[5], wav[6], wav[7]);

    g_rcnt[i] = 0;
    g_ccnt[i] = 0;
}

// Kernel 2 (edge-parallel): bucket each edge by row AND by col. No heavy atomics.
__global__ void bucket_kernel(const int* __restrict__ rows,
                              const int* __restrict__ cols,
                              const float* __restrict__ vals) {
    int e = blockIdx.x * blockDim.x + threadIdx.x;
    if (e >= NNZ_E) return;

    int r = rows[e];
    int c = cols[e];
    unsigned vbits = __float_as_uint(vals[e]);

    int pr = atomicAdd(&g_rcnt[r], 1);
    if (pr < CAP) g_rbuf[(size_t)r * CAP + pr] = make_uint2((unsigned)c, vbits);

    int pc = atomicAdd(&g_ccnt[c], 1);
    if (pc < CAP) g_cbuf[(size_t)c * CAP + pc] = make_uint2((unsigned)r, vbits);
}

// Kernel 3: LTx[c,d] = sum_{edges with col=c} v * x[r,d].
// Half-warp per node: sub = lane>>4 picks the node, d = lane&15 picks the dim.
__global__ void col_pass_kernel(const float* __restrict__ x) {
    int w = (blockIdx.x * blockDim.x + threadIdx.x) >> 5;
    int lane = threadIdx.x & 31;
    int node = w * 2 + (lane >> 4);
    if (node >= N_NODES) return;
    int d = lane & 15;

    int cnt = g_ccnt[node];
    cnt = cnt < CAP ? cnt : CAP;

    const uint2* buf = g_cbuf + (size_t)node * CAP;
    float acc = 0.f;
#pragma unroll 4
    for (int i = 0; i < cnt; i++) {
        uint2 ev = buf[i];                    // half-warp broadcast load
        int   r = (int)ev.x;
        float v = __uint_as_float(ev.y);
        acc = fmaf(v, x[(size_t)r * D_DIM + d], acc);
    }
    g_cw[(size_t)node * CW_STRIDE + d] = acc; // coalesced 64B per half-warp
}

// Kernel 4: out[r,d,f] = sum_{edges with row=r} v * LTx[c,d] * wav[c,f].
// Warp per row: lane -> (d = lane>>1, q = lane&1), 4 outputs per lane, one v4 store.
__global__ void row_pass_kernel(float* __restrict__ out) {
    int w = (blockIdx.x * blockDim.x + threadIdx.x) >> 5;
    if (w >= N_NODES) return;
    int lane = threadIdx.x & 31;

    int cnt = g_rcnt[w];
    cnt = cnt < CAP ? cnt : CAP;

    int d = lane >> 1;
    int q = lane & 1;

    float4 acc = make_float4(0.f, 0.f, 0.f, 0.f);
    const uint2* buf = g_rbuf + (size_t)w * CAP;

#pragma unroll 4
    for (int i = 0; i < cnt; i++) {
        uint2 ev = buf[i];                    // warp-broadcast load
        int   c = (int)ev.x;
        float v = __uint_as_float(ev.y);
        const float* cw = g_cw + (size_t)c * CW_STRIDE;
        float  ltx = cw[d];
        float4 wv  = reinterpret_cast<const float4*>(cw + D_DIM)[q];
        float s = v * ltx;
        acc.x = fmaf(s, wv.x, acc.x);
        acc.y = fmaf(s, wv.y, acc.y);
        acc.z = fmaf(s, wv.z, acc.z);
        acc.w = fmaf(s, wv.w, acc.w);
    }

    reinterpret_cast<float4*>(out + (size_t)w * (D_DIM * F_FILT))[lane] = acc;
}

extern "C" void kernel_launch(void* const* d_in, const int* in_sizes, int n_in,
                              void* d_out, int out_size) {
    const float* x    = (const float*)d_in[0];
    const int*   rows = (const int*)  d_in[1];
    const int*   cols = (const int*)  d_in[2];
    const float* vals = (const float*)d_in[3];
    const float* eig  = (const float*)d_in[4];
    float* out = (float*)d_out;

    prep_kernel<<<(N_NODES + 255) / 256, 256>>>(eig);

    bucket_kernel<<<(NNZ_E + 255) / 256, 256>>>(rows, cols, vals);

    {   // half-warp per node -> 16 threads per node
        long long threads = (long long)N_NODES * 16;
        int blocks = (int)((threads + 255) / 256);
        col_pass_kernel<<<blocks, 256>>>(x);
    }
    {   // warp per row
        long long threads = (long long)N_NODES * 32;
        int blocks = (int)((threads + 255) / 256);
        row_pass_kernel<<<blocks, 256>>>(out);
    }
}